// round 1
// baseline (speedup 1.0000x reference)
#include <cuda_runtime.h>
#include <math.h>
#include <stdint.h>

#define N_TOK 16384
#define D 512
#define VOCAB 96

// ---------------- device scratch (no allocations allowed) ----------------
__device__ float2 g_mod1[VOCAB * D];   // cis(2*pi*char*d/(96*512)), layout [char][d]
__device__ float2 g_mod2[VOCAB * D];   // cis(4*pi*1.7*char*d/(96*512))
__device__ float2 g_filt[D];
__device__ float  g_w1[D];
__device__ float  g_w2[D];
__device__ float4 g_phtab[D];          // cos(phase), sin(phase), cos(2phase), sin(2phase)
__device__ float4 g_tok[N_TOK * 3];    // v0: wf1.x wf1.y wf2.x wf2.y
                                       // v1: cos(cpm) sin(cpm) cos(1.3cpm) sin(1.3cpm)
                                       // v2: cos(.7cpm) sin(.7cpm) 0 0
__device__ float  g_x[(size_t)N_TOK * D];   // rotated/normalized real state
__device__ float  g_xw[(size_t)N_TOK * D];  // x @ W^T + b

// ---------------- K0: precompute all tables + per-token scalars ----------------
__global__ void setup_kernel(const int* __restrict__ char_idx,
                             const int* __restrict__ positions) {
    const int idx = blockIdx.x * blockDim.x + threadIdx.x;
    const double PI = 3.14159265358979323846;

    if (idx < VOCAB * D) {
        int c = idx / D, d = idx % D;
        double prod = (double)c * (double)d;
        double a1 = 2.0 * PI * prod / ((double)VOCAB * (double)D);
        double s, co;
        sincos(a1, &s, &co);
        g_mod1[idx] = make_float2((float)co, (float)s);
        double a2 = (4.0 * PI * 1.7) * prod / ((double)VOCAB * (double)D);
        sincos(a2, &s, &co);
        g_mod2[idx] = make_float2((float)co, (float)s);
    }

    if (idx < D) {
        double kv = (double)idx + 1.0;
        double arg1 = 1.5 * atan(log(kv + 1e-10));
        double s1, c1, s2, c2;
        sincos(arg1, &s1, &c1);
        double arg2 = 0.8 * sin(0.1 * kv);
        sincos(arg2, &s2, &c2);
        g_filt[idx] = make_float2((float)(0.7 * c1 + 0.3 * c2),
                                  (float)(0.7 * s1 + 0.3 * s2));
        g_w1[idx] = (float)(0.6 + 0.4 * sin(0.1 * (double)idx));
        g_w2[idx] = (float)(0.4 + 0.6 * cos(0.15 * (double)idx));
        double ph = 2.0 * PI * (double)idx / (double)D;
        double sp, cp, s2p, c2p;
        sincos(ph, &sp, &cp);
        sincos(2.0 * ph, &s2p, &c2p);
        g_phtab[idx] = make_float4((float)cp, (float)sp, (float)c2p, (float)s2p);
    }

    if (idx < N_TOK) {
        int ci = char_idx[idx];
        double lam = (double)ci / (double)VOCAB;
        double t = (double)positions[idx] / 100.0;
        double omega = 2.0 * PI * 1.5;
        double kwav = 2.0 * PI / 1.7;
        double ph1 = omega * t - kwav * lam + 0.8 * lam * lam;
        double ph2 = omega * t * 1.5 - kwav * lam * 0.7 + 0.8 * lam * lam * 1.3;
        double a1 = sin(omega * t + 1.5 * lam);
        double a2 = cos(omega * t * 0.8 + 1.5 * lam * 1.2);
        double s, c;
        sincos(ph1, &s, &c);
        float wf1x = (float)(a1 * c), wf1y = (float)(a1 * s);
        sincos(ph2, &s, &c);
        float wf2x = (float)(a2 * c), wf2y = (float)(a2 * s);
        g_tok[idx * 3 + 0] = make_float4(wf1x, wf1y, wf2x, wf2y);

        double cpm = (double)ci * 0.01;
        double s0, c0, s1, c1, s2, c2;
        sincos(cpm, &s0, &c0);
        sincos(cpm * 1.3, &s1, &c1);
        sincos(cpm * 0.7, &s2, &c2);
        g_tok[idx * 3 + 1] = make_float4((float)c0, (float)s0, (float)c1, (float)s1);
        g_tok[idx * 3 + 2] = make_float4((float)c2, (float)s2, 0.f, 0.f);
    }
}

// ---------------- K1: build state, filter, normalize, SO(4)->real ----------------
__global__ __launch_bounds__(512) void state_kernel(const int* __restrict__ char_idx) {
    const int n = blockIdx.x;
    const int d = threadIdx.x;
    const int c = __ldg(&char_idx[n]);

    const float4 v0 = g_tok[n * 3 + 0];
    const float2 m1 = g_mod1[c * D + d];
    const float2 m2 = g_mod2[c * D + d];
    const float w1 = g_w1[d], w2 = g_w2[d];

    // u = wf1*m1, v = wf2*m2 (complex mults)
    float ux = v0.x * m1.x - v0.y * m1.y;
    float uy = v0.x * m1.y + v0.y * m1.x;
    float vx = v0.z * m2.x - v0.w * m2.y;
    float vy = v0.z * m2.y + v0.w * m2.x;
    float sx = w1 * ux + w2 * vx;
    float sy = w1 * uy + w2 * vy;

    const float2 f = g_filt[d];
    float tx = sx * f.x - sy * f.y;
    float ty = sx * f.y + sy * f.x;

    float sq = tx * tx + ty * ty;

    __shared__ float warpsum[16];
    __shared__ float s_rinv;
    float r = sq;
    #pragma unroll
    for (int o = 16; o > 0; o >>= 1) r += __shfl_xor_sync(0xffffffffu, r, o);
    if ((threadIdx.x & 31) == 0) warpsum[threadIdx.x >> 5] = r;
    __syncthreads();
    if (threadIdx.x < 32) {
        float t = (threadIdx.x < 16) ? warpsum[threadIdx.x] : 0.0f;
        #pragma unroll
        for (int o = 8; o > 0; o >>= 1) t += __shfl_xor_sync(0xffffffffu, t, o);
        if (threadIdx.x == 0) s_rinv = 1.0f / (sqrtf(t) + 1e-8f);
    }
    __syncthreads();

    const float ct = 0.995004165278025766f;   // cos(0.1)
    const float st = 0.0998334166468281523f;  // sin(0.1)
    g_x[(size_t)n * D + d] = (tx * ct - ty * st) * s_rinv;
}

// ---------------- K2: fp32 SIMT GEMM  xw = x @ W^T + b ----------------
#define BM 128
#define BN 128
#define BK 16

__global__ __launch_bounds__(256) void gemm_kernel(const float* __restrict__ W,
                                                   const float* __restrict__ bias) {
    __shared__ float As[BK][BM];
    __shared__ float Bs[BK][BN];

    const int bm = blockIdx.y * BM;
    const int bn = blockIdx.x * BN;
    const int tid = threadIdx.x;
    const int tm = (tid >> 4) * 8;   // 0..120
    const int tn = (tid & 15) * 8;   // 0..120

    float acc[8][8];
    #pragma unroll
    for (int i = 0; i < 8; i++)
        #pragma unroll
        for (int j = 0; j < 8; j++) acc[i][j] = 0.0f;

    const float* Ag = g_x + (size_t)bm * D;
    const float* Bg = W + (size_t)bn * D;

    for (int kk = 0; kk < D; kk += BK) {
        #pragma unroll
        for (int l = 0; l < 2; l++) {
            int idx = tid + l * 256;        // 0..511
            int row = idx >> 2;             // 0..127
            int c4 = (idx & 3) * 4;         // 0,4,8,12
            float4 va = *(const float4*)(Ag + (size_t)row * D + kk + c4);
            As[c4 + 0][row] = va.x;
            As[c4 + 1][row] = va.y;
            As[c4 + 2][row] = va.z;
            As[c4 + 3][row] = va.w;
            float4 vb = *(const float4*)(Bg + (size_t)row * D + kk + c4);
            Bs[c4 + 0][row] = vb.x;
            Bs[c4 + 1][row] = vb.y;
            Bs[c4 + 2][row] = vb.z;
            Bs[c4 + 3][row] = vb.w;
        }
        __syncthreads();
        #pragma unroll
        for (int k = 0; k < BK; k++) {
            float a[8], bb[8];
            *(float4*)(a)      = *(const float4*)&As[k][tm];
            *(float4*)(a + 4)  = *(const float4*)&As[k][tm + 4];
            *(float4*)(bb)     = *(const float4*)&Bs[k][tn];
            *(float4*)(bb + 4) = *(const float4*)&Bs[k][tn + 4];
            #pragma unroll
            for (int i = 0; i < 8; i++)
                #pragma unroll
                for (int j = 0; j < 8; j++)
                    acc[i][j] = fmaf(a[i], bb[j], acc[i][j]);
        }
        __syncthreads();
    }

    #pragma unroll
    for (int i = 0; i < 8; i++) {
        const size_t row = (size_t)(bm + tm + i);
        #pragma unroll
        for (int j = 0; j < 8; j += 4) {
            float4 o;
            o.x = acc[i][j + 0] + bias[bn + tn + j + 0];
            o.y = acc[i][j + 1] + bias[bn + tn + j + 1];
            o.z = acc[i][j + 2] + bias[bn + tn + j + 2];
            o.w = acc[i][j + 3] + bias[bn + tn + j + 3];
            *(float4*)(g_xw + row * D + bn + tn + j) = o;
        }
    }
}

// ---------------- K3: LayerNorm + noise + quaternion embedding ----------------
__global__ __launch_bounds__(512) void finish_kernel(const int* __restrict__ char_idx,
                                                     const float* __restrict__ gamma,
                                                     const float* __restrict__ beta_ln,
                                                     const float* __restrict__ noise,
                                                     const float* __restrict__ sem,
                                                     float4* __restrict__ out) {
    const int n = blockIdx.x;
    const int d = threadIdx.x;

    const float x = g_xw[(size_t)n * D + d];

    __shared__ float wsum[16], wsum2[16];
    __shared__ float s_mu, s_rstd;
    float s = x, ss = x * x;
    #pragma unroll
    for (int o = 16; o > 0; o >>= 1) {
        s += __shfl_xor_sync(0xffffffffu, s, o);
        ss += __shfl_xor_sync(0xffffffffu, ss, o);
    }
    if ((threadIdx.x & 31) == 0) {
        wsum[threadIdx.x >> 5] = s;
        wsum2[threadIdx.x >> 5] = ss;
    }
    __syncthreads();
    if (threadIdx.x < 32) {
        float t = (threadIdx.x < 16) ? wsum[threadIdx.x] : 0.0f;
        float t2 = (threadIdx.x < 16) ? wsum2[threadIdx.x] : 0.0f;
        #pragma unroll
        for (int o = 8; o > 0; o >>= 1) {
            t += __shfl_xor_sync(0xffffffffu, t, o);
            t2 += __shfl_xor_sync(0xffffffffu, t2, o);
        }
        if (threadIdx.x == 0) {
            float mu = t * (1.0f / (float)D);
            float var = t2 * (1.0f / (float)D) - mu * mu;
            s_mu = mu;
            s_rstd = rsqrtf(var + 1e-5f);
        }
    }
    __syncthreads();

    const float y = (x - s_mu) * s_rstd * gamma[d] + beta_ln[d]
                  + 0.01f * noise[(size_t)n * D + d];

    const int c = __ldg(&char_idx[n]);
    const float sw0 = __ldg(&sem[c * 4 + 0]);
    const float sw1 = __ldg(&sem[c * 4 + 1]);
    const float sw2 = __ldg(&sem[c * 4 + 2]);

    const float4 t1 = g_tok[n * 3 + 1];  // cos(cpm), sin(cpm), cos(1.3cpm), sin(1.3cpm)
    const float4 t2v = g_tok[n * 3 + 2]; // cos(.7cpm), sin(.7cpm)
    const float4 ph = g_phtab[d];        // cosP, sinP, cos2P, sin2P

    const float q1 = y * sw0 * (ph.x * t1.x - ph.y * t1.y);   // cos(phase+cpm)
    const float q2 = y * sw1 * (ph.y * t1.z + ph.x * t1.w);   // sin(phase+1.3cpm)
    const float q3 = y * sw2 * (ph.z * t2v.x - ph.w * t2v.y); // cos(2phase+0.7cpm)

    out[(size_t)n * D + d] = make_float4(y, q1, q2, q3);
}

// ---------------- launch ----------------
extern "C" void kernel_launch(void* const* d_in, const int* in_sizes, int n_in,
                              void* d_out, int out_size) {
    const int*   char_idx  = (const int*)d_in[0];
    const int*   positions = (const int*)d_in[1];
    const float* W         = (const float*)d_in[2];
    const float* b         = (const float*)d_in[3];
    const float* gamma     = (const float*)d_in[4];
    const float* beta_ln   = (const float*)d_in[5];
    const float* noise     = (const float*)d_in[6];
    const float* sem       = (const float*)d_in[7];
    float4* out = (float4*)d_out;

    setup_kernel<<<(VOCAB * D + 255) / 256, 256>>>(char_idx, positions);
    state_kernel<<<N_TOK, D>>>(char_idx);
    gemm_kernel<<<dim3(D / BN, N_TOK / BM), 256>>>(W, b);
    finish_kernel<<<N_TOK, D>>>(char_idx, gamma, beta_ln, noise, sem, out);
}

// round 3
// speedup vs baseline: 2.6201x; 2.6201x over previous
#include <cuda_runtime.h>
#include <math.h>
#include <stdint.h>

#define N_TOK 16384
#define D 512
#define VOCAB 96

// ---------------- device scratch ----------------
__device__ float2 g_u1[VOCAB * D];   // w1[d]*mod1[c,d]*filt[d]
__device__ float2 g_u2[VOCAB * D];   // w2[d]*mod2[c,d]*filt[d]
__device__ float4 g_V[VOCAB * D];    // (V1r, V1i, V2r, V2i) = U @ W^T
__device__ float4 g_S[VOCAB];        // (S11, S22, S12r, S12i)
__device__ float4 g_phtab[D];        // cosP, sinP, cos2P, sin2P
__device__ float4 g_wf[N_TOK];       // wf1r, wf1i, wf2r, wf2i
__device__ float4 g_tokA[N_TOK];     // cos(cpm), sin(cpm), cos(1.3cpm), sin(1.3cpm)
__device__ float2 g_tokB[N_TOK];     // cos(.7cpm), sin(.7cpm)
__device__ float4 g_coef[N_TOK];     // p1, q1, p2, q2  (rinv folded in)

// ---------------- K0: u-tables, phase table, per-token wave scalars ----------------
__global__ void setup_kernel(const int* __restrict__ char_idx,
                             const int* __restrict__ positions) {
    const int idx = blockIdx.x * blockDim.x + threadIdx.x;
    const double PI = 3.14159265358979323846;

    if (idx < VOCAB * D) {
        int c = idx / D, d = idx % D;
        double prod = (double)c * (double)d;
        double s, co;

        // filt[d]
        double kv = (double)d + 1.0;
        double s1, c1, s2, c2;
        sincos(1.5 * atan(log(kv + 1e-10)), &s1, &c1);
        sincos(0.8 * sin(0.1 * kv), &s2, &c2);
        double fr = 0.7 * c1 + 0.3 * c2;
        double fi = 0.7 * s1 + 0.3 * s2;

        double w1 = 0.6 + 0.4 * sin(0.1 * (double)d);
        double w2 = 0.4 + 0.6 * cos(0.15 * (double)d);

        // mod1 = cis(2*pi*c*d/(96*512))
        sincos(2.0 * PI * prod / ((double)VOCAB * (double)D), &s, &co);
        double u1r = w1 * (co * fr - s * fi);
        double u1i = w1 * (co * fi + s * fr);
        g_u1[idx] = make_float2((float)u1r, (float)u1i);

        // mod2 = cis(4*pi*1.7*c*d/(96*512))
        sincos((4.0 * PI * 1.7) * prod / ((double)VOCAB * (double)D), &s, &co);
        double u2r = w2 * (co * fr - s * fi);
        double u2i = w2 * (co * fi + s * fr);
        g_u2[idx] = make_float2((float)u2r, (float)u2i);
    }

    if (idx < D) {
        double ph = 2.0 * PI * (double)idx / (double)D;
        double sp, cp, s2p, c2p;
        sincos(ph, &sp, &cp);
        sincos(2.0 * ph, &s2p, &c2p);
        g_phtab[idx] = make_float4((float)cp, (float)sp, (float)c2p, (float)s2p);
    }

    if (idx < N_TOK) {
        int ci = char_idx[idx];
        double lam = (double)ci / (double)VOCAB;
        double t = (double)positions[idx] / 100.0;
        double omega = 2.0 * PI * 1.5;
        double kwav = 2.0 * PI / 1.7;
        double ph1 = omega * t - kwav * lam + 0.8 * lam * lam;
        double ph2 = omega * t * 1.5 - kwav * lam * 0.7 + 0.8 * lam * lam * 1.3;
        double a1 = sin(omega * t + 1.5 * lam);
        double a2 = cos(omega * t * 0.8 + 1.5 * lam * 1.2);
        double s, c;
        sincos(ph1, &s, &c);
        float wf1r = (float)(a1 * c), wf1i = (float)(a1 * s);
        sincos(ph2, &s, &c);
        float wf2r = (float)(a2 * c), wf2i = (float)(a2 * s);
        g_wf[idx] = make_float4(wf1r, wf1i, wf2r, wf2i);

        double cpm = (double)ci * 0.01;
        double s0, c0, sb, cb, sc, cc;
        sincos(cpm, &s0, &c0);
        sincos(cpm * 1.3, &sb, &cb);
        sincos(cpm * 0.7, &sc, &cc);
        g_tokA[idx] = make_float4((float)c0, (float)s0, (float)cb, (float)sb);
        g_tokB[idx] = make_float2((float)cc, (float)sc);
    }
}

// ---------------- K1: per-char Gram sums S ----------------
__global__ __launch_bounds__(256) void sreduce_kernel() {
    const int c = blockIdx.x;
    const int tid = threadIdx.x;
    float s11 = 0.f, s22 = 0.f, s12r = 0.f, s12i = 0.f;
    #pragma unroll
    for (int k = 0; k < 2; k++) {
        int d = tid + k * 256;
        float2 a = g_u1[c * D + d];
        float2 b = g_u2[c * D + d];
        s11 += a.x * a.x + a.y * a.y;
        s22 += b.x * b.x + b.y * b.y;
        s12r += a.x * b.x + a.y * b.y;   // Re(u1*conj(u2))
        s12i += a.y * b.x - a.x * b.y;   // Im(u1*conj(u2))
    }
    __shared__ float sm[4][8];
    #pragma unroll
    for (int o = 16; o > 0; o >>= 1) {
        s11 += __shfl_xor_sync(0xffffffffu, s11, o);
        s22 += __shfl_xor_sync(0xffffffffu, s22, o);
        s12r += __shfl_xor_sync(0xffffffffu, s12r, o);
        s12i += __shfl_xor_sync(0xffffffffu, s12i, o);
    }
    if ((tid & 31) == 0) {
        int w = tid >> 5;
        sm[0][w] = s11; sm[1][w] = s22; sm[2][w] = s12r; sm[3][w] = s12i;
    }
    __syncthreads();
    if (tid == 0) {
        float a = 0, b = 0, cc = 0, dd = 0;
        #pragma unroll
        for (int w = 0; w < 8; w++) { a += sm[0][w]; b += sm[1][w]; cc += sm[2][w]; dd += sm[3][w]; }
        g_S[c] = make_float4(a, b, cc, dd);
    }
}

// ---------------- K2: V = U @ W^T (96x512 complex, two tables) ----------------
__global__ __launch_bounds__(512) void vgemm_kernel(const float* __restrict__ W) {
    const int c = blockIdx.x;
    const int dp = threadIdx.x;     // output column d'

    __shared__ float2 su1[D];
    __shared__ float2 su2[D];
    su1[dp] = g_u1[c * D + dp];
    su2[dp] = g_u2[c * D + dp];
    __syncthreads();

    float v1r = 0.f, v1i = 0.f, v2r = 0.f, v2i = 0.f;
    const float* wr = W + (size_t)dp * D;
    #pragma unroll 4
    for (int d = 0; d < D; d += 8) {
        float4 wa = *(const float4*)(wr + d);
        float4 wb = *(const float4*)(wr + d + 4);
        float wv[8] = {wa.x, wa.y, wa.z, wa.w, wb.x, wb.y, wb.z, wb.w};
        #pragma unroll
        for (int j = 0; j < 8; j++) {
            float2 a = su1[d + j];
            float2 b = su2[d + j];
            v1r = fmaf(a.x, wv[j], v1r);
            v1i = fmaf(a.y, wv[j], v1i);
            v2r = fmaf(b.x, wv[j], v2r);
            v2i = fmaf(b.y, wv[j], v2i);
        }
    }
    g_V[c * D + dp] = make_float4(v1r, v1i, v2r, v2i);
}

// ---------------- K3: per-token coefficients (closed-form norm + rotation) ----------------
__global__ __launch_bounds__(256) void coef_kernel(const int* __restrict__ char_idx) {
    const int n = blockIdx.x * blockDim.x + threadIdx.x;
    if (n >= N_TOK) return;
    const int c = char_idx[n];
    const float4 wf = g_wf[n];
    const float4 S = g_S[c];

    float n1 = wf.x * wf.x + wf.y * wf.y;
    float n2 = wf.z * wf.z + wf.w * wf.w;
    float Ar = wf.x * wf.z + wf.y * wf.w;   // Re(wf1*conj(wf2))
    float Ai = wf.y * wf.z - wf.x * wf.w;   // Im(wf1*conj(wf2))
    float nrm2 = n1 * S.x + n2 * S.y + 2.0f * (Ar * S.z - Ai * S.w);
    float rinv = 1.0f / (sqrtf(nrm2) + 1e-8f);

    const float ct = 0.995004165278025766f;   // cos(0.1)
    const float st = 0.0998334166468281523f;  // sin(0.1)
    float p1 = (wf.x * ct - wf.y * st) * rinv;
    float q1 = -(wf.y * ct + wf.x * st) * rinv;
    float p2 = (wf.z * ct - wf.w * st) * rinv;
    float q2 = -(wf.w * ct + wf.z * st) * rinv;
    g_coef[n] = make_float4(p1, q1, p2, q2);
}

// ---------------- K4: fused xw + LayerNorm + noise + quaternion ----------------
__global__ __launch_bounds__(128) void main_kernel(const int* __restrict__ char_idx,
                                                   const float* __restrict__ bias,
                                                   const float* __restrict__ gamma,
                                                   const float* __restrict__ beta_ln,
                                                   const float* __restrict__ noise,
                                                   const float* __restrict__ sem,
                                                   float4* __restrict__ out) {
    const int n = blockIdx.x;
    const int tid = threadIdx.x;
    const int c = __ldg(&char_idx[n]);
    const float4 cf = g_coef[n];

    float xw[4];
    #pragma unroll
    for (int k = 0; k < 4; k++) {
        const int d = tid + k * 128;
        float4 v = __ldg(&g_V[c * D + d]);
        xw[k] = fmaf(cf.x, v.x, fmaf(cf.y, v.y, fmaf(cf.z, v.z, cf.w * v.w)))
              + __ldg(&bias[d]);
    }

    // block reduction of sum / sumsq over 512 values
    float s = xw[0] + xw[1] + xw[2] + xw[3];
    float ss = xw[0] * xw[0] + xw[1] * xw[1] + xw[2] * xw[2] + xw[3] * xw[3];
    __shared__ float sm1[4], sm2[4];
    __shared__ float s_mu, s_rstd;
    #pragma unroll
    for (int o = 16; o > 0; o >>= 1) {
        s += __shfl_xor_sync(0xffffffffu, s, o);
        ss += __shfl_xor_sync(0xffffffffu, ss, o);
    }
    if ((tid & 31) == 0) { sm1[tid >> 5] = s; sm2[tid >> 5] = ss; }
    __syncthreads();
    if (tid == 0) {
        float t = sm1[0] + sm1[1] + sm1[2] + sm1[3];
        float t2 = sm2[0] + sm2[1] + sm2[2] + sm2[3];
        float mu = t * (1.0f / (float)D);
        s_mu = mu;
        s_rstd = rsqrtf(t2 * (1.0f / (float)D) - mu * mu + 1e-5f);
    }
    __syncthreads();
    const float mu = s_mu, rstd = s_rstd;

    const float sw0 = __ldg(&sem[c * 4 + 0]);
    const float sw1 = __ldg(&sem[c * 4 + 1]);
    const float sw2 = __ldg(&sem[c * 4 + 2]);
    const float4 tA = g_tokA[n];
    const float2 tB = g_tokB[n];

    #pragma unroll
    for (int k = 0; k < 4; k++) {
        const int d = tid + k * 128;
        float y = (xw[k] - mu) * rstd * __ldg(&gamma[d]) + __ldg(&beta_ln[d])
                + 0.01f * __ldg(&noise[(size_t)n * D + d]);
        float4 ph = g_phtab[d];
        float4 o;
        o.x = y;
        o.y = y * sw0 * (ph.x * tA.x - ph.y * tA.y);   // cos(phase + cpm)
        o.z = y * sw1 * (ph.y * tA.z + ph.x * tA.w);   // sin(phase + 1.3cpm)
        o.w = y * sw2 * (ph.z * tB.x - ph.w * tB.y);   // cos(2phase + 0.7cpm)
        out[(size_t)n * D + d] = o;
    }
}

// ---------------- launch ----------------
extern "C" void kernel_launch(void* const* d_in, const int* in_sizes, int n_in,
                              void* d_out, int out_size) {
    const int*   char_idx  = (const int*)d_in[0];
    const int*   positions = (const int*)d_in[1];
    const float* W         = (const float*)d_in[2];
    const float* b         = (const float*)d_in[3];
    const float* gamma     = (const float*)d_in[4];
    const float* beta_ln   = (const float*)d_in[5];
    const float* noise     = (const float*)d_in[6];
    const float* sem       = (const float*)d_in[7];
    float4* out = (float4*)d_out;

    setup_kernel<<<(VOCAB * D + 255) / 256, 256>>>(char_idx, positions);
    sreduce_kernel<<<VOCAB, 256>>>();
    vgemm_kernel<<<VOCAB, D>>>(W);
    coef_kernel<<<(N_TOK + 255) / 256, 256>>>(char_idx);
    main_kernel<<<N_TOK, 128>>>(char_idx, b, gamma, beta_ln, noise, sem, out);
}

// round 4
// speedup vs baseline: 2.7862x; 1.0634x over previous
#include <cuda_runtime.h>
#include <math.h>
#include <stdint.h>

#define N_TOK 16384
#define D 512
#define VOCAB 96

// ---------------- device scratch ----------------
__device__ float4 g_V[VOCAB * D];    // (V1r, V1i, V2r, V2i) = U @ W^T
__device__ float4 g_S[VOCAB];        // (S11, S22, S12r, S12i)
__device__ float4 g_phtab[D];        // cosP, sinP, cos2P, sin2P
__device__ float4 g_cols[D];         // bias, gamma, beta, 0
__device__ float4 g_wf[N_TOK];       // wf1r, wf1i, wf2r, wf2i
__device__ float4 g_tokA[N_TOK];     // cos(cpm), sin(cpm), cos(1.3cpm), sin(1.3cpm)
__device__ float2 g_tokB[N_TOK];     // cos(.7cpm), sin(.7cpm)

// per-(char,d) u-values, fp32 (angles are small; sincosf is plenty accurate)
__device__ __forceinline__ void make_u(int c, int d, float2& u1, float2& u2) {
    const float PI = 3.14159265358979323846f;
    float kv = (float)d + 1.0f;
    float s1, c1, s2, c2;
    __sincosf(0.0f, &s1, &c1); // placeholder avoided; use accurate versions below
    sincosf(1.5f * atanf(logf(kv + 1e-10f)), &s1, &c1);
    sincosf(0.8f * sinf(0.1f * kv), &s2, &c2);
    float fr = 0.7f * c1 + 0.3f * c2;
    float fi = 0.7f * s1 + 0.3f * s2;
    float w1 = 0.6f + 0.4f * sinf(0.1f * (float)d);
    float w2 = 0.4f + 0.6f * cosf(0.15f * (float)d);

    float prod = (float)c * (float)d;
    float s, co;
    sincosf(2.0f * PI * prod * (1.0f / ((float)VOCAB * (float)D)), &s, &co);
    u1 = make_float2(w1 * (co * fr - s * fi), w1 * (co * fi + s * fr));
    sincosf((4.0f * PI * 1.7f) * prod * (1.0f / ((float)VOCAB * (float)D)), &s, &co);
    u2 = make_float2(w2 * (co * fr - s * fi), w2 * (co * fi + s * fr));
}

// ---------------- K0: per-token scalars + per-d tables ----------------
__global__ void token_setup_kernel(const int* __restrict__ char_idx,
                                   const int* __restrict__ positions,
                                   const float* __restrict__ bias,
                                   const float* __restrict__ gamma,
                                   const float* __restrict__ beta_ln) {
    const int idx = blockIdx.x * blockDim.x + threadIdx.x;
    const float PI = 3.14159265358979323846f;

    if (idx < D) {
        float ph = 2.0f * PI * (float)idx * (1.0f / (float)D);
        float sp, cp, s2p, c2p;
        sincosf(ph, &sp, &cp);
        sincosf(2.0f * ph, &s2p, &c2p);
        g_phtab[idx] = make_float4(cp, sp, c2p, s2p);
        g_cols[idx] = make_float4(bias[idx], gamma[idx], beta_ln[idx], 0.f);
    }

    if (idx < N_TOK) {
        int ci = char_idx[idx];
        float lam = (float)ci * (1.0f / (float)VOCAB);
        float t = (float)positions[idx] * 0.01f;
        float omega = 2.0f * PI * 1.5f;
        float kwav = 2.0f * PI / 1.7f;
        float ph1 = omega * t - kwav * lam + 0.8f * lam * lam;
        float ph2 = omega * t * 1.5f - kwav * lam * 0.7f + 0.8f * lam * lam * 1.3f;
        float a1 = sinf(omega * t + 1.5f * lam);
        float a2 = cosf(omega * t * 0.8f + 1.5f * lam * 1.2f);
        float s, c;
        sincosf(ph1, &s, &c);
        float wf1r = a1 * c, wf1i = a1 * s;
        sincosf(ph2, &s, &c);
        float wf2r = a2 * c, wf2i = a2 * s;
        g_wf[idx] = make_float4(wf1r, wf1i, wf2r, wf2i);

        float cpm = (float)ci * 0.01f;
        float s0, c0, sb, cb, sc, cc;
        sincosf(cpm, &s0, &c0);
        sincosf(cpm * 1.3f, &sb, &cb);
        sincosf(cpm * 0.7f, &sc, &cc);
        g_tokA[idx] = make_float4(c0, s0, cb, sb);
        g_tokB[idx] = make_float2(cc, sc);
    }
}

// ---------------- K1: V = U @ W^T + per-char Gram sums (fused) ----------------
// grid (96, 2), 256 threads. Block (c, h) computes V columns [h*256, h*256+256).
__global__ __launch_bounds__(256) void vgemm_kernel(const float* __restrict__ W) {
    const int c = blockIdx.x;
    const int half = blockIdx.y;
    const int tid = threadIdx.x;

    __shared__ float2 su1[D];
    __shared__ float2 su2[D];
    #pragma unroll
    for (int k = 0; k < 2; k++) {
        int d = tid + k * 256;
        float2 a, b;
        make_u(c, d, a, b);
        su1[d] = a;
        su2[d] = b;
    }
    __syncthreads();

    if (half == 0) {
        // Gram sums (block 0 only)
        float s11 = 0.f, s22 = 0.f, s12r = 0.f, s12i = 0.f;
        #pragma unroll
        for (int k = 0; k < 2; k++) {
            int d = tid + k * 256;
            float2 a = su1[d], b = su2[d];
            s11 += a.x * a.x + a.y * a.y;
            s22 += b.x * b.x + b.y * b.y;
            s12r += a.x * b.x + a.y * b.y;
            s12i += a.y * b.x - a.x * b.y;
        }
        __shared__ float sm[4][8];
        #pragma unroll
        for (int o = 16; o > 0; o >>= 1) {
            s11 += __shfl_xor_sync(0xffffffffu, s11, o);
            s22 += __shfl_xor_sync(0xffffffffu, s22, o);
            s12r += __shfl_xor_sync(0xffffffffu, s12r, o);
            s12i += __shfl_xor_sync(0xffffffffu, s12i, o);
        }
        if ((tid & 31) == 0) {
            int w = tid >> 5;
            sm[0][w] = s11; sm[1][w] = s22; sm[2][w] = s12r; sm[3][w] = s12i;
        }
        __syncthreads();
        if (tid == 0) {
            float a = 0, b = 0, cc = 0, dd = 0;
            #pragma unroll
            for (int w = 0; w < 8; w++) { a += sm[0][w]; b += sm[1][w]; cc += sm[2][w]; dd += sm[3][w]; }
            g_S[c] = make_float4(a, b, cc, dd);
        }
    }

    const int dp = half * 256 + tid;
    float v1r = 0.f, v1i = 0.f, v2r = 0.f, v2i = 0.f;
    const float* wr = W + (size_t)dp * D;
    #pragma unroll 4
    for (int d = 0; d < D; d += 8) {
        float4 wa = *(const float4*)(wr + d);
        float4 wb = *(const float4*)(wr + d + 4);
        float wv[8] = {wa.x, wa.y, wa.z, wa.w, wb.x, wb.y, wb.z, wb.w};
        #pragma unroll
        for (int j = 0; j < 8; j++) {
            float2 a = su1[d + j];
            float2 b = su2[d + j];
            v1r = fmaf(a.x, wv[j], v1r);
            v1i = fmaf(a.y, wv[j], v1i);
            v2r = fmaf(b.x, wv[j], v2r);
            v2i = fmaf(b.y, wv[j], v2i);
        }
    }
    g_V[c * D + dp] = make_float4(v1r, v1i, v2r, v2i);
}

// ---------------- K2: fused coef + xw + LayerNorm + noise + quaternion ----------------
// One token per WARP. 256 threads = 8 tokens/block, grid = N_TOK/8.
__global__ __launch_bounds__(256) void main_kernel(const int* __restrict__ char_idx,
                                                   const float* __restrict__ noise,
                                                   const float* __restrict__ sem,
                                                   float4* __restrict__ out) {
    const int lane = threadIdx.x & 31;
    const int n = blockIdx.x * 8 + (threadIdx.x >> 5);
    const int c = __ldg(&char_idx[n]);

    // per-token coefficients (all lanes, broadcast loads)
    const float4 wf = g_wf[n];
    const float4 S = g_S[c];
    float n1 = wf.x * wf.x + wf.y * wf.y;
    float n2 = wf.z * wf.z + wf.w * wf.w;
    float Ar = wf.x * wf.z + wf.y * wf.w;
    float Ai = wf.y * wf.z - wf.x * wf.w;
    float nrm2 = n1 * S.x + n2 * S.y + 2.0f * (Ar * S.z - Ai * S.w);
    float rinv = 1.0f / (sqrtf(nrm2) + 1e-8f);
    const float ct = 0.995004165278025766f;
    const float st = 0.0998334166468281523f;
    const float p1 = (wf.x * ct - wf.y * st) * rinv;
    const float q1 = -(wf.y * ct + wf.x * st) * rinv;
    const float p2 = (wf.z * ct - wf.w * st) * rinv;
    const float q2 = -(wf.w * ct + wf.z * st) * rinv;

    // xw for 16 columns per lane
    float xw[16];
    float s = 0.f, ss = 0.f;
    #pragma unroll
    for (int j = 0; j < 16; j++) {
        const int d = lane + j * 32;
        float4 v = __ldg(&g_V[c * D + d]);
        float x = fmaf(p1, v.x, fmaf(q1, v.y, fmaf(p2, v.z, q2 * v.w)))
                + __ldg(&g_cols[d]).x;
        xw[j] = x;
        s += x;
        ss = fmaf(x, x, ss);
    }
    #pragma unroll
    for (int o = 16; o > 0; o >>= 1) {
        s += __shfl_xor_sync(0xffffffffu, s, o);
        ss += __shfl_xor_sync(0xffffffffu, ss, o);
    }
    const float mu = s * (1.0f / (float)D);
    const float rstd = rsqrtf(ss * (1.0f / (float)D) - mu * mu + 1e-5f);

    const float sw0 = __ldg(&sem[c * 4 + 0]);
    const float sw1 = __ldg(&sem[c * 4 + 1]);
    const float sw2 = __ldg(&sem[c * 4 + 2]);
    const float4 tA = g_tokA[n];
    const float2 tB = g_tokB[n];

    const float* nrow = noise + (size_t)n * D;
    float4* orow = out + (size_t)n * D;

    #pragma unroll
    for (int j = 0; j < 16; j++) {
        const int d = lane + j * 32;
        float4 col = __ldg(&g_cols[d]);   // bias, gamma, beta
        float y = (xw[j] - mu) * rstd * col.y + col.z + 0.01f * __ldcs(&nrow[d]);
        float4 ph = __ldg(&g_phtab[d]);
        float4 o;
        o.x = y;
        o.y = y * sw0 * (ph.x * tA.x - ph.y * tA.y);   // cos(phase + cpm)
        o.z = y * sw1 * (ph.y * tA.z + ph.x * tA.w);   // sin(phase + 1.3cpm)
        o.w = y * sw2 * (ph.z * tB.x - ph.w * tB.y);   // cos(2phase + 0.7cpm)
        __stcs(&orow[d], o);
    }
}

// ---------------- launch ----------------
extern "C" void kernel_launch(void* const* d_in, const int* in_sizes, int n_in,
                              void* d_out, int out_size) {
    const int*   char_idx  = (const int*)d_in[0];
    const int*   positions = (const int*)d_in[1];
    const float* W         = (const float*)d_in[2];
    const float* b         = (const float*)d_in[3];
    const float* gamma     = (const float*)d_in[4];
    const float* beta_ln   = (const float*)d_in[5];
    const float* noise     = (const float*)d_in[6];
    const float* sem       = (const float*)d_in[7];
    float4* out = (float4*)d_out;

    token_setup_kernel<<<(N_TOK + 255) / 256, 256>>>(char_idx, positions, b, gamma, beta_ln);
    vgemm_kernel<<<dim3(VOCAB, 2), 256>>>(W);
    main_kernel<<<N_TOK / 8, 256>>>(char_idx, noise, sem, out);
}

// round 5
// speedup vs baseline: 2.7968x; 1.0038x over previous
#include <cuda_runtime.h>
#include <math.h>
#include <stdint.h>

#define N_TOK 16384
#define D 512
#define VOCAB 96

// ---------------- device scratch ----------------
__device__ float4 g_V[VOCAB * D];    // (V1r, V1i, V2r, V2i) = U @ W^T
__device__ float4 g_S[VOCAB];        // (S11, S22, S12r, S12i)
__device__ float4 g_phtab[D];        // cosP, sinP, cos2P, sin2P
__device__ float4 g_cols[D];         // bias, gamma, beta, 0
__device__ float4 g_wf[N_TOK];       // wf1r, wf1i, wf2r, wf2i
__device__ float4 g_tokA[N_TOK];     // cos(cpm), sin(cpm), cos(1.3cpm), sin(1.3cpm)
__device__ float2 g_tokB[N_TOK];     // cos(.7cpm), sin(.7cpm)

// per-(char,d) u-values, fp32
__device__ __forceinline__ void make_u(int c, int d, float2& u1, float2& u2) {
    const float PI = 3.14159265358979323846f;
    float kv = (float)d + 1.0f;
    float s1, c1, s2, c2;
    sincosf(1.5f * atanf(logf(kv + 1e-10f)), &s1, &c1);
    sincosf(0.8f * sinf(0.1f * kv), &s2, &c2);
    float fr = 0.7f * c1 + 0.3f * c2;
    float fi = 0.7f * s1 + 0.3f * s2;
    float w1 = 0.6f + 0.4f * sinf(0.1f * (float)d);
    float w2 = 0.4f + 0.6f * cosf(0.15f * (float)d);

    float prod = (float)c * (float)d;
    float s, co;
    sincosf(2.0f * PI * prod * (1.0f / ((float)VOCAB * (float)D)), &s, &co);
    u1 = make_float2(w1 * (co * fr - s * fi), w1 * (co * fi + s * fr));
    sincosf((4.0f * PI * 1.7f) * prod * (1.0f / ((float)VOCAB * (float)D)), &s, &co);
    u2 = make_float2(w2 * (co * fr - s * fi), w2 * (co * fi + s * fr));
}

// ---------------- K0: fused token setup + per-d tables + V gemm + Gram sums ----
// grid (96, 2), 256 threads. Block (c, h) computes V columns [h*256, h*256+256).
// Flat thread id additionally covers token-scalar setup (16384) and d-tables (512).
__global__ __launch_bounds__(256) void vgemm_kernel(const int* __restrict__ char_idx,
                                                    const int* __restrict__ positions,
                                                    const float* __restrict__ W,
                                                    const float* __restrict__ bias,
                                                    const float* __restrict__ gamma,
                                                    const float* __restrict__ beta_ln) {
    const int c = blockIdx.x;
    const int half = blockIdx.y;
    const int tid = threadIdx.x;
    const int gid = (blockIdx.y * 96 + blockIdx.x) * 256 + tid;
    const float PI = 3.14159265358979323846f;

    // ---- embedded per-d tables ----
    if (gid < D) {
        float ph = 2.0f * PI * (float)gid * (1.0f / (float)D);
        float sp, cp, s2p, c2p;
        sincosf(ph, &sp, &cp);
        sincosf(2.0f * ph, &s2p, &c2p);
        g_phtab[gid] = make_float4(cp, sp, c2p, s2p);
        g_cols[gid] = make_float4(bias[gid], gamma[gid], beta_ln[gid], 0.f);
    }

    // ---- embedded per-token scalars ----
    if (gid < N_TOK) {
        int ci = char_idx[gid];
        float lam = (float)ci * (1.0f / (float)VOCAB);
        float t = (float)positions[gid] * 0.01f;
        float omega = 2.0f * PI * 1.5f;
        float kwav = 2.0f * PI / 1.7f;
        float ph1 = omega * t - kwav * lam + 0.8f * lam * lam;
        float ph2 = omega * t * 1.5f - kwav * lam * 0.7f + 0.8f * lam * lam * 1.3f;
        float a1 = sinf(omega * t + 1.5f * lam);
        float a2 = cosf(omega * t * 0.8f + 1.5f * lam * 1.2f);
        float s, cc;
        sincosf(ph1, &s, &cc);
        float wf1r = a1 * cc, wf1i = a1 * s;
        sincosf(ph2, &s, &cc);
        float wf2r = a2 * cc, wf2i = a2 * s;
        g_wf[gid] = make_float4(wf1r, wf1i, wf2r, wf2i);

        float cpm = (float)ci * 0.01f;
        float s0, c0, sb, cb, sc, ccc;
        sincosf(cpm, &s0, &c0);
        sincosf(cpm * 1.3f, &sb, &cb);
        sincosf(cpm * 0.7f, &sc, &ccc);
        g_tokA[gid] = make_float4(c0, s0, cb, sb);
        g_tokB[gid] = make_float2(ccc, sc);
    }

    // ---- u tables for this char ----
    __shared__ float2 su1[D];
    __shared__ float2 su2[D];
    #pragma unroll
    for (int k = 0; k < 2; k++) {
        int d = tid + k * 256;
        float2 a, b;
        make_u(c, d, a, b);
        su1[d] = a;
        su2[d] = b;
    }
    __syncthreads();

    if (half == 0) {
        float s11 = 0.f, s22 = 0.f, s12r = 0.f, s12i = 0.f;
        #pragma unroll
        for (int k = 0; k < 2; k++) {
            int d = tid + k * 256;
            float2 a = su1[d], b = su2[d];
            s11 += a.x * a.x + a.y * a.y;
            s22 += b.x * b.x + b.y * b.y;
            s12r += a.x * b.x + a.y * b.y;
            s12i += a.y * b.x - a.x * b.y;
        }
        __shared__ float sm[4][8];
        #pragma unroll
        for (int o = 16; o > 0; o >>= 1) {
            s11 += __shfl_xor_sync(0xffffffffu, s11, o);
            s22 += __shfl_xor_sync(0xffffffffu, s22, o);
            s12r += __shfl_xor_sync(0xffffffffu, s12r, o);
            s12i += __shfl_xor_sync(0xffffffffu, s12i, o);
        }
        if ((tid & 31) == 0) {
            int w = tid >> 5;
            sm[0][w] = s11; sm[1][w] = s22; sm[2][w] = s12r; sm[3][w] = s12i;
        }
        __syncthreads();
        if (tid == 0) {
            float a = 0, b = 0, cc = 0, dd = 0;
            #pragma unroll
            for (int w = 0; w < 8; w++) { a += sm[0][w]; b += sm[1][w]; cc += sm[2][w]; dd += sm[3][w]; }
            g_S[c] = make_float4(a, b, cc, dd);
        }
    }

    const int dp = half * 256 + tid;
    float v1r = 0.f, v1i = 0.f, v2r = 0.f, v2i = 0.f;
    const float* wr = W + (size_t)dp * D;
    #pragma unroll 4
    for (int d = 0; d < D; d += 8) {
        float4 wa = *(const float4*)(wr + d);
        float4 wb = *(const float4*)(wr + d + 4);
        float wv[8] = {wa.x, wa.y, wa.z, wa.w, wb.x, wb.y, wb.z, wb.w};
        #pragma unroll
        for (int j = 0; j < 8; j++) {
            float2 a = su1[d + j];
            float2 b = su2[d + j];
            v1r = fmaf(a.x, wv[j], v1r);
            v1i = fmaf(a.y, wv[j], v1i);
            v2r = fmaf(b.x, wv[j], v2r);
            v2i = fmaf(b.y, wv[j], v2i);
        }
    }
    g_V[c * D + dp] = make_float4(v1r, v1i, v2r, v2i);
}

// ---------------- K1: fused coef + xw + LayerNorm + noise + quaternion ----------
// One token per WARP, 512 threads = 16 tokens/block; per-d tables staged in smem.
__global__ __launch_bounds__(512) void main_kernel(const int* __restrict__ char_idx,
                                                   const float* __restrict__ noise,
                                                   const float* __restrict__ sem,
                                                   float4* __restrict__ out) {
    __shared__ float4 s_cols[D];   // bias, gamma, beta
    __shared__ float4 s_ph[D];     // cosP, sinP, cos2P, sin2P

    const int tid = threadIdx.x;
    const int lane = tid & 31;
    const int n = blockIdx.x * 16 + (tid >> 5);

    s_cols[tid] = g_cols[tid];
    s_ph[tid] = g_phtab[tid];
    const int c = __ldg(&char_idx[n]);
    const float4 wf = g_wf[n];
    const float4 S = __ldg(&g_S[c]);
    __syncthreads();

    // per-token coefficients (redundant per lane; ~30 flops)
    float n1 = wf.x * wf.x + wf.y * wf.y;
    float n2 = wf.z * wf.z + wf.w * wf.w;
    float Ar = wf.x * wf.z + wf.y * wf.w;
    float Ai = wf.y * wf.z - wf.x * wf.w;
    float nrm2 = n1 * S.x + n2 * S.y + 2.0f * (Ar * S.z - Ai * S.w);
    float rinv = 1.0f / (sqrtf(nrm2) + 1e-8f);
    const float ct = 0.995004165278025766f;
    const float st = 0.0998334166468281523f;
    const float p1 = (wf.x * ct - wf.y * st) * rinv;
    const float q1 = -(wf.y * ct + wf.x * st) * rinv;
    const float p2 = (wf.z * ct - wf.w * st) * rinv;
    const float q2 = -(wf.w * ct + wf.z * st) * rinv;

    // xw for 16 columns per lane (V rows stream from L2; lanes coalesced)
    float xw[16];
    float s = 0.f, ss = 0.f;
    const float4* vrow = g_V + c * D;
    #pragma unroll
    for (int j = 0; j < 16; j++) {
        const int d = lane + j * 32;
        float4 v = __ldg(&vrow[d]);
        float x = fmaf(p1, v.x, fmaf(q1, v.y, fmaf(p2, v.z, q2 * v.w)))
                + s_cols[d].x;
        xw[j] = x;
        s += x;
        ss = fmaf(x, x, ss);
    }
    #pragma unroll
    for (int o = 16; o > 0; o >>= 1) {
        s += __shfl_xor_sync(0xffffffffu, s, o);
        ss += __shfl_xor_sync(0xffffffffu, ss, o);
    }
    const float mu = s * (1.0f / (float)D);
    const float rstd = rsqrtf(ss * (1.0f / (float)D) - mu * mu + 1e-5f);

    const float sw0 = __ldg(&sem[c * 4 + 0]);
    const float sw1 = __ldg(&sem[c * 4 + 1]);
    const float sw2 = __ldg(&sem[c * 4 + 2]);
    const float4 tA = g_tokA[n];
    const float2 tB = g_tokB[n];

    const float* nrow = noise + (size_t)n * D;
    float4* orow = out + (size_t)n * D;

    #pragma unroll
    for (int j = 0; j < 16; j++) {
        const int d = lane + j * 32;
        float4 col = s_cols[d];
        float y = (xw[j] - mu) * rstd * col.y + col.z + 0.01f * __ldcs(&nrow[d]);
        float4 ph = s_ph[d];
        float4 o;
        o.x = y;
        o.y = y * sw0 * (ph.x * tA.x - ph.y * tA.y);   // cos(phase + cpm)
        o.z = y * sw1 * (ph.y * tA.z + ph.x * tA.w);   // sin(phase + 1.3cpm)
        o.w = y * sw2 * (ph.z * tB.x - ph.w * tB.y);   // cos(2phase + 0.7cpm)
        __stcs(&orow[d], o);
    }
}

// ---------------- launch ----------------
extern "C" void kernel_launch(void* const* d_in, const int* in_sizes, int n_in,
                              void* d_out, int out_size) {
    const int*   char_idx  = (const int*)d_in[0];
    const int*   positions = (const int*)d_in[1];
    const float* W         = (const float*)d_in[2];
    const float* b         = (const float*)d_in[3];
    const float* gamma     = (const float*)d_in[4];
    const float* beta_ln   = (const float*)d_in[5];
    const float* noise     = (const float*)d_in[6];
    const float* sem       = (const float*)d_in[7];
    float4* out = (float4*)d_out;

    vgemm_kernel<<<dim3(VOCAB, 2), 256>>>(char_idx, positions, W, b, gamma, beta_ln);
    main_kernel<<<N_TOK / 16, 512>>>(char_idx, noise, sem, out);
}

// round 6
// speedup vs baseline: 4.6524x; 1.6635x over previous
#include <cuda_runtime.h>
#include <math.h>
#include <stdint.h>

#define N_TOK 16384
#define D 512
#define VOCAB 96

// ---------------- device scratch ----------------
__device__ float4 g_V[VOCAB * D];    // (V1r, V1i, V2r, V2i) = U @ W^T
__device__ float4 g_S[VOCAB];        // (S11, S22, S12r, S12i)
__device__ float4 g_phtab[D];        // cosP, sinP, cos2P, sin2P
__device__ float4 g_cols[D];         // bias, gamma, beta, 0
__device__ float4 g_wf[N_TOK];       // wf1r, wf1i, wf2r, wf2i
__device__ float4 g_tokA[N_TOK];     // cos(cpm), sin(cpm), cos(1.3cpm), sin(1.3cpm)
__device__ float2 g_tokB[N_TOK];     // cos(.7cpm), sin(.7cpm)

// per-(char,d) u-values, fp32
__device__ __forceinline__ void make_u(int c, int d, float2& u1, float2& u2) {
    const float PI = 3.14159265358979323846f;
    float kv = (float)d + 1.0f;
    float s1, c1, s2, c2;
    sincosf(1.5f * atanf(logf(kv + 1e-10f)), &s1, &c1);
    sincosf(0.8f * sinf(0.1f * kv), &s2, &c2);
    float fr = 0.7f * c1 + 0.3f * c2;
    float fi = 0.7f * s1 + 0.3f * s2;
    float w1 = 0.6f + 0.4f * sinf(0.1f * (float)d);
    float w2 = 0.4f + 0.6f * cosf(0.15f * (float)d);

    float prod = (float)c * (float)d;
    float s, co;
    sincosf(2.0f * PI * prod * (1.0f / ((float)VOCAB * (float)D)), &s, &co);
    u1 = make_float2(w1 * (co * fr - s * fi), w1 * (co * fi + s * fr));
    sincosf((4.0f * PI * 1.7f) * prod * (1.0f / ((float)VOCAB * (float)D)), &s, &co);
    u2 = make_float2(w2 * (co * fr - s * fi), w2 * (co * fi + s * fr));
}

// ---------------- K0: fused setup + tiled V gemm + Gram sums ----------------
// grid (96, 2), 256 threads. Block (c, h) computes V columns [h*256, h*256+256).
__global__ __launch_bounds__(256) void vgemm_kernel(const int* __restrict__ char_idx,
                                                    const int* __restrict__ positions,
                                                    const float* __restrict__ W,
                                                    const float* __restrict__ bias,
                                                    const float* __restrict__ gamma,
                                                    const float* __restrict__ beta_ln) {
    const int c = blockIdx.x;
    const int half = blockIdx.y;
    const int tid = threadIdx.x;
    const int gid = (blockIdx.y * 96 + blockIdx.x) * 256 + tid;
    const float PI = 3.14159265358979323846f;

    __shared__ float2 su1[D];
    __shared__ float2 su2[D];
    __shared__ float tile[256][33];   // W sub-tile, padded stride
    __shared__ float sm[4][8];

    // ---- embedded per-d tables ----
    if (gid < D) {
        float ph = 2.0f * PI * (float)gid * (1.0f / (float)D);
        float sp, cp, s2p, c2p;
        sincosf(ph, &sp, &cp);
        sincosf(2.0f * ph, &s2p, &c2p);
        g_phtab[gid] = make_float4(cp, sp, c2p, s2p);
        g_cols[gid] = make_float4(bias[gid], gamma[gid], beta_ln[gid], 0.f);
    }

    // ---- embedded per-token scalars ----
    if (gid < N_TOK) {
        int ci = char_idx[gid];
        float lam = (float)ci * (1.0f / (float)VOCAB);
        float t = (float)positions[gid] * 0.01f;
        float omega = 2.0f * PI * 1.5f;
        float kwav = 2.0f * PI / 1.7f;
        float ph1 = omega * t - kwav * lam + 0.8f * lam * lam;
        float ph2 = omega * t * 1.5f - kwav * lam * 0.7f + 0.8f * lam * lam * 1.3f;
        float a1 = sinf(omega * t + 1.5f * lam);
        float a2 = cosf(omega * t * 0.8f + 1.5f * lam * 1.2f);
        float s, cc;
        sincosf(ph1, &s, &cc);
        float wf1r = a1 * cc, wf1i = a1 * s;
        sincosf(ph2, &s, &cc);
        float wf2r = a2 * cc, wf2i = a2 * s;
        g_wf[gid] = make_float4(wf1r, wf1i, wf2r, wf2i);

        float cpm = (float)ci * 0.01f;
        float s0, c0, sb, cb, sc, ccc;
        sincosf(cpm, &s0, &c0);
        sincosf(cpm * 1.3f, &sb, &cb);
        sincosf(cpm * 0.7f, &sc, &ccc);
        g_tokA[gid] = make_float4(c0, s0, cb, sb);
        g_tokB[gid] = make_float2(ccc, sc);
    }

    // ---- u tables for this char ----
    #pragma unroll
    for (int k = 0; k < 2; k++) {
        int d = tid + k * 256;
        float2 a, b;
        make_u(c, d, a, b);
        su1[d] = a;
        su2[d] = b;
    }
    __syncthreads();

    if (half == 0) {
        float s11 = 0.f, s22 = 0.f, s12r = 0.f, s12i = 0.f;
        #pragma unroll
        for (int k = 0; k < 2; k++) {
            int d = tid + k * 256;
            float2 a = su1[d], b = su2[d];
            s11 += a.x * a.x + a.y * a.y;
            s22 += b.x * b.x + b.y * b.y;
            s12r += a.x * b.x + a.y * b.y;
            s12i += a.y * b.x - a.x * b.y;
        }
        #pragma unroll
        for (int o = 16; o > 0; o >>= 1) {
            s11 += __shfl_xor_sync(0xffffffffu, s11, o);
            s22 += __shfl_xor_sync(0xffffffffu, s22, o);
            s12r += __shfl_xor_sync(0xffffffffu, s12r, o);
            s12i += __shfl_xor_sync(0xffffffffu, s12i, o);
        }
        if ((tid & 31) == 0) {
            int w = tid >> 5;
            sm[0][w] = s11; sm[1][w] = s22; sm[2][w] = s12r; sm[3][w] = s12i;
        }
        __syncthreads();
        if (tid == 0) {
            float a = 0, b = 0, cc = 0, dd = 0;
            #pragma unroll
            for (int w = 0; w < 8; w++) { a += sm[0][w]; b += sm[1][w]; cc += sm[2][w]; dd += sm[3][w]; }
            g_S[c] = make_float4(a, b, cc, dd);
        }
    }

    // ---- tiled GEMM: V[c, dpbase + tid] over 16 chunks of 32 k-values ----
    const int dpbase = half * 256;
    float v1r = 0.f, v1i = 0.f, v2r = 0.f, v2i = 0.f;

    #pragma unroll 1
    for (int chunk = 0; chunk < 16; chunk++) {
        const int dk = chunk * 32;
        __syncthreads();
        // coalesced load of W[dpbase..dpbase+256)[dk..dk+32)
        #pragma unroll
        for (int l = 0; l < 8; l++) {
            int f = tid + l * 256;            // float4 index 0..2047
            int row = f >> 3, col4 = (f & 7) * 4;
            float4 w = *(const float4*)(W + (size_t)(dpbase + row) * D + dk + col4);
            tile[row][col4 + 0] = w.x;
            tile[row][col4 + 1] = w.y;
            tile[row][col4 + 2] = w.z;
            tile[row][col4 + 3] = w.w;
        }
        __syncthreads();
        #pragma unroll
        for (int k = 0; k < 32; k++) {
            float wv = tile[tid][k];
            float2 a = su1[dk + k];
            float2 b = su2[dk + k];
            v1r = fmaf(a.x, wv, v1r);
            v1i = fmaf(a.y, wv, v1i);
            v2r = fmaf(b.x, wv, v2r);
            v2i = fmaf(b.y, wv, v2i);
        }
    }
    g_V[c * D + dpbase + tid] = make_float4(v1r, v1i, v2r, v2i);
}

// ---------------- K1: fused coef + xw + LayerNorm + noise + quaternion ----------
// One token per 128-thread group; 4 tokens per 512-thread block.
__global__ __launch_bounds__(512, 2) void main_kernel(const int* __restrict__ char_idx,
                                                      const float* __restrict__ noise,
                                                      const float* __restrict__ sem,
                                                      float4* __restrict__ out) {
    __shared__ float4 s_cols[D];
    __shared__ float4 s_ph[D];
    __shared__ float red_s[16], red_ss[16];

    const int tid = threadIdx.x;
    const int grp = tid >> 7;        // 0..3 token group
    const int gt = tid & 127;        // thread within group
    const int lane = tid & 31;
    const int wid = tid >> 5;        // 0..15
    const int n = blockIdx.x * 4 + grp;

    s_cols[tid] = g_cols[tid];
    s_ph[tid] = g_phtab[tid];
    const int c = __ldg(&char_idx[n]);
    const float4 wf = g_wf[n];
    const float4 S = __ldg(&g_S[c]);
    __syncthreads();

    // per-token coefficients (redundant per thread; ~30 flops)
    float n1 = wf.x * wf.x + wf.y * wf.y;
    float n2 = wf.z * wf.z + wf.w * wf.w;
    float Ar = wf.x * wf.z + wf.y * wf.w;
    float Ai = wf.y * wf.z - wf.x * wf.w;
    float nrm2 = n1 * S.x + n2 * S.y + 2.0f * (Ar * S.z - Ai * S.w);
    float rinv = 1.0f / (sqrtf(nrm2) + 1e-8f);
    const float ct = 0.995004165278025766f;
    const float st = 0.0998334166468281523f;
    const float p1 = (wf.x * ct - wf.y * st) * rinv;
    const float q1 = -(wf.y * ct + wf.x * st) * rinv;
    const float p2 = (wf.z * ct - wf.w * st) * rinv;
    const float q2 = -(wf.w * ct + wf.z * st) * rinv;

    // 4 columns per thread, fully coalesced V reads
    const float4* vrow = g_V + c * D;
    float xw[4];
    float s = 0.f, ss = 0.f;
    #pragma unroll
    for (int k = 0; k < 4; k++) {
        const int d = k * 128 + gt;
        float4 v = __ldg(&vrow[d]);
        float x = fmaf(p1, v.x, fmaf(q1, v.y, fmaf(p2, v.z, q2 * v.w)))
                + s_cols[d].x;
        xw[k] = x;
        s += x;
        ss = fmaf(x, x, ss);
    }
    #pragma unroll
    for (int o = 16; o > 0; o >>= 1) {
        s += __shfl_xor_sync(0xffffffffu, s, o);
        ss += __shfl_xor_sync(0xffffffffu, ss, o);
    }
    if (lane == 0) { red_s[wid] = s; red_ss[wid] = ss; }
    __syncthreads();
    const int rb = grp * 4;
    float ts = red_s[rb] + red_s[rb + 1] + red_s[rb + 2] + red_s[rb + 3];
    float tss = red_ss[rb] + red_ss[rb + 1] + red_ss[rb + 2] + red_ss[rb + 3];
    const float mu = ts * (1.0f / (float)D);
    const float rstd = rsqrtf(tss * (1.0f / (float)D) - mu * mu + 1e-5f);

    const float sw0 = __ldg(&sem[c * 4 + 0]);
    const float sw1 = __ldg(&sem[c * 4 + 1]);
    const float sw2 = __ldg(&sem[c * 4 + 2]);
    const float4 tA = g_tokA[n];
    const float2 tB = g_tokB[n];

    const float* nrow = noise + (size_t)n * D;
    float4* orow = out + (size_t)n * D;

    #pragma unroll
    for (int k = 0; k < 4; k++) {
        const int d = k * 128 + gt;
        float4 col = s_cols[d];
        float y = (xw[k] - mu) * rstd * col.y + col.z + 0.01f * __ldcs(&nrow[d]);
        float4 ph = s_ph[d];
        float4 o;
        o.x = y;
        o.y = y * sw0 * (ph.x * tA.x - ph.y * tA.y);   // cos(phase + cpm)
        o.z = y * sw1 * (ph.y * tA.z + ph.x * tA.w);   // sin(phase + 1.3cpm)
        o.w = y * sw2 * (ph.z * tB.x - ph.w * tB.y);   // cos(2phase + 0.7cpm)
        __stcs(&orow[d], o);
    }
}

// ---------------- launch ----------------
extern "C" void kernel_launch(void* const* d_in, const int* in_sizes, int n_in,
                              void* d_out, int out_size) {
    const int*   char_idx  = (const int*)d_in[0];
    const int*   positions = (const int*)d_in[1];
    const float* W         = (const float*)d_in[2];
    const float* b         = (const float*)d_in[3];
    const float* gamma     = (const float*)d_in[4];
    const float* beta_ln   = (const float*)d_in[5];
    const float* noise     = (const float*)d_in[6];
    const float* sem       = (const float*)d_in[7];
    float4* out = (float4*)d_out;

    vgemm_kernel<<<dim3(VOCAB, 2), 256>>>(char_idx, positions, W, b, gamma, beta_ln);
    main_kernel<<<N_TOK / 4, 512>>>(char_idx, noise, sem, out);
}

// round 7
// speedup vs baseline: 4.6895x; 1.0080x over previous
#include <cuda_runtime.h>
#include <math.h>
#include <stdint.h>

#define N_TOK 16384
#define D 512
#define VOCAB 96

// ---------------- device scratch ----------------
__device__ float4 g_U[VOCAB * D];    // (u1r, u1i, u2r, u2i) per (char, d)
__device__ float4 g_V[VOCAB * D];    // (V1r, V1i, V2r, V2i) = U @ W^T
__device__ float4 g_S[VOCAB];        // (S11, S22, S12r, S12i)
__device__ float4 g_phtab[D];        // cosP, sinP, cos2P, sin2P
__device__ float4 g_cols[D];         // bias, gamma, beta, 0
__device__ float4 g_wf[N_TOK];       // wf1r, wf1i, wf2r, wf2i
__device__ float4 g_tokA[N_TOK];     // cos(cpm), sin(cpm), cos(1.3cpm), sin(1.3cpm)
__device__ float2 g_tokB[N_TOK];     // cos(.7cpm), sin(.7cpm)

// ---------------- K0: all trig, fully parallel ----------------
// grid 192 x 256 = 49152 threads: U entries (49152), token scalars (16384), d tables (512)
__global__ __launch_bounds__(256) void setup_kernel(const int* __restrict__ char_idx,
                                                    const int* __restrict__ positions,
                                                    const float* __restrict__ bias,
                                                    const float* __restrict__ gamma,
                                                    const float* __restrict__ beta_ln) {
    const int gid = blockIdx.x * blockDim.x + threadIdx.x;
    const float PI = 3.14159265358979323846f;

    // ---- U table entry ----
    {
        int c = gid / D, d = gid % D;   // gid < 49152 always (grid sized exactly)
        float kv = (float)d + 1.0f;
        float s1, c1, s2, c2;
        sincosf(1.5f * atanf(logf(kv + 1e-10f)), &s1, &c1);
        sincosf(0.8f * sinf(0.1f * kv), &s2, &c2);
        float fr = 0.7f * c1 + 0.3f * c2;
        float fi = 0.7f * s1 + 0.3f * s2;
        float w1 = 0.6f + 0.4f * sinf(0.1f * (float)d);
        float w2 = 0.4f + 0.6f * cosf(0.15f * (float)d);

        float prod = (float)c * (float)d;
        float s, co;
        sincosf(2.0f * PI * prod * (1.0f / ((float)VOCAB * (float)D)), &s, &co);
        float u1r = w1 * (co * fr - s * fi), u1i = w1 * (co * fi + s * fr);
        sincosf((4.0f * PI * 1.7f) * prod * (1.0f / ((float)VOCAB * (float)D)), &s, &co);
        float u2r = w2 * (co * fr - s * fi), u2i = w2 * (co * fi + s * fr);
        g_U[gid] = make_float4(u1r, u1i, u2r, u2i);
    }

    if (gid < D) {
        float ph = 2.0f * PI * (float)gid * (1.0f / (float)D);
        float sp, cp, s2p, c2p;
        sincosf(ph, &sp, &cp);
        sincosf(2.0f * ph, &s2p, &c2p);
        g_phtab[gid] = make_float4(cp, sp, c2p, s2p);
        g_cols[gid] = make_float4(bias[gid], gamma[gid], beta_ln[gid], 0.f);
    }

    if (gid < N_TOK) {
        int ci = char_idx[gid];
        float lam = (float)ci * (1.0f / (float)VOCAB);
        float t = (float)positions[gid] * 0.01f;
        float omega = 2.0f * PI * 1.5f;
        float kwav = 2.0f * PI / 1.7f;
        float ph1 = omega * t - kwav * lam + 0.8f * lam * lam;
        float ph2 = omega * t * 1.5f - kwav * lam * 0.7f + 0.8f * lam * lam * 1.3f;
        float a1 = sinf(omega * t + 1.5f * lam);
        float a2 = cosf(omega * t * 0.8f + 1.5f * lam * 1.2f);
        float s, cc;
        sincosf(ph1, &s, &cc);
        float wf1r = a1 * cc, wf1i = a1 * s;
        sincosf(ph2, &s, &cc);
        float wf2r = a2 * cc, wf2i = a2 * s;
        g_wf[gid] = make_float4(wf1r, wf1i, wf2r, wf2i);

        float cpm = (float)ci * 0.01f;
        float s0, c0, sb, cb, sc, ccc;
        sincosf(cpm, &s0, &c0);
        sincosf(cpm * 1.3f, &sb, &cb);
        sincosf(cpm * 0.7f, &sc, &ccc);
        g_tokA[gid] = make_float4(c0, s0, cb, sb);
        g_tokB[gid] = make_float2(ccc, sc);
    }
}

// ---------------- K1: tiled V gemm + Gram sums ----------------
// grid (96, 4), 128 threads. Block (c, q) computes V columns [q*128, q*128+128).
__global__ __launch_bounds__(128) void vgemm_kernel(const float* __restrict__ W) {
    const int c = blockIdx.x;
    const int q = blockIdx.y;
    const int tid = threadIdx.x;

    __shared__ float4 su[D];          // u1r,u1i,u2r,u2i for this char
    __shared__ float tile[128][33];   // W sub-tile, padded stride
    __shared__ float sm[4][4];

    #pragma unroll
    for (int l = 0; l < 4; l++)
        su[tid + l * 128] = __ldg(&g_U[c * D + tid + l * 128]);
    __syncthreads();

    if (q == 0) {
        // Gram sums over 512 entries (128 threads x 4)
        float s11 = 0.f, s22 = 0.f, s12r = 0.f, s12i = 0.f;
        #pragma unroll
        for (int l = 0; l < 4; l++) {
            float4 u = su[tid + l * 128];
            s11 += u.x * u.x + u.y * u.y;
            s22 += u.z * u.z + u.w * u.w;
            s12r += u.x * u.z + u.y * u.w;
            s12i += u.y * u.z - u.x * u.w;
        }
        #pragma unroll
        for (int o = 16; o > 0; o >>= 1) {
            s11 += __shfl_xor_sync(0xffffffffu, s11, o);
            s22 += __shfl_xor_sync(0xffffffffu, s22, o);
            s12r += __shfl_xor_sync(0xffffffffu, s12r, o);
            s12i += __shfl_xor_sync(0xffffffffu, s12i, o);
        }
        if ((tid & 31) == 0) {
            int w = tid >> 5;
            sm[0][w] = s11; sm[1][w] = s22; sm[2][w] = s12r; sm[3][w] = s12i;
        }
        __syncthreads();
        if (tid == 0) {
            g_S[c] = make_float4(sm[0][0] + sm[0][1] + sm[0][2] + sm[0][3],
                                 sm[1][0] + sm[1][1] + sm[1][2] + sm[1][3],
                                 sm[2][0] + sm[2][1] + sm[2][2] + sm[2][3],
                                 sm[3][0] + sm[3][1] + sm[3][2] + sm[3][3]);
        }
    }

    // ---- tiled GEMM: V[c, q*128 + tid], 16 chunks of 32 k-values ----
    const int dpbase = q * 128;
    float v1r = 0.f, v1i = 0.f, v2r = 0.f, v2i = 0.f;

    #pragma unroll 1
    for (int chunk = 0; chunk < 16; chunk++) {
        const int dk = chunk * 32;
        __syncthreads();
        // coalesced load of W[dpbase..dpbase+128)[dk..dk+32): 1024 float4, 8/thread
        #pragma unroll
        for (int l = 0; l < 8; l++) {
            int f = tid + l * 128;
            int row = f >> 3, col4 = (f & 7) * 4;
            float4 w = *(const float4*)(W + (size_t)(dpbase + row) * D + dk + col4);
            tile[row][col4 + 0] = w.x;
            tile[row][col4 + 1] = w.y;
            tile[row][col4 + 2] = w.z;
            tile[row][col4 + 3] = w.w;
        }
        __syncthreads();
        #pragma unroll
        for (int k = 0; k < 32; k++) {
            float wv = tile[tid][k];
            float4 u = su[dk + k];       // uniform across warp -> broadcast
            v1r = fmaf(u.x, wv, v1r);
            v1i = fmaf(u.y, wv, v1i);
            v2r = fmaf(u.z, wv, v2r);
            v2i = fmaf(u.w, wv, v2i);
        }
    }
    g_V[c * D + dpbase + tid] = make_float4(v1r, v1i, v2r, v2i);
}

// ---------------- K2: fused coef + xw + LayerNorm + noise + quaternion ----------
// One token per 128-thread group; 2 tokens per 256-thread block; tables in registers.
__global__ __launch_bounds__(256, 3) void main_kernel(const int* __restrict__ char_idx,
                                                      const float* __restrict__ noise,
                                                      const float* __restrict__ sem,
                                                      float4* __restrict__ out) {
    __shared__ float red_s[8], red_ss[8];

    const int tid = threadIdx.x;
    const int grp = tid >> 7;        // 0..1 token group
    const int gt = tid & 127;        // thread within group
    const int lane = tid & 31;
    const int wid = tid >> 5;        // 0..7
    const int n = blockIdx.x * 2 + grp;

    // register-resident per-d tables (d = k*128 + gt, fixed per thread)
    float4 colr[4], phr[4];
    #pragma unroll
    for (int k = 0; k < 4; k++) {
        colr[k] = __ldg(&g_cols[k * 128 + gt]);
        phr[k]  = __ldg(&g_phtab[k * 128 + gt]);
    }

    const int c = __ldg(&char_idx[n]);
    const float4 wf = __ldg(&g_wf[n]);
    const float4 S = __ldg(&g_S[c]);

    // per-token coefficients
    float n1 = wf.x * wf.x + wf.y * wf.y;
    float n2 = wf.z * wf.z + wf.w * wf.w;
    float Ar = wf.x * wf.z + wf.y * wf.w;
    float Ai = wf.y * wf.z - wf.x * wf.w;
    float nrm2 = n1 * S.x + n2 * S.y + 2.0f * (Ar * S.z - Ai * S.w);
    float rinv = 1.0f / (sqrtf(nrm2) + 1e-8f);
    const float ct = 0.995004165278025766f;
    const float st = 0.0998334166468281523f;
    const float p1 = (wf.x * ct - wf.y * st) * rinv;
    const float q1 = -(wf.y * ct + wf.x * st) * rinv;
    const float p2 = (wf.z * ct - wf.w * st) * rinv;
    const float q2 = -(wf.w * ct + wf.z * st) * rinv;

    // 4 columns per thread, coalesced V reads
    const float4* vrow = g_V + c * D;
    float xw[4];
    float s = 0.f, ss = 0.f;
    #pragma unroll
    for (int k = 0; k < 4; k++) {
        const int d = k * 128 + gt;
        float4 v = __ldg(&vrow[d]);
        float x = fmaf(p1, v.x, fmaf(q1, v.y, fmaf(p2, v.z, q2 * v.w))) + colr[k].x;
        xw[k] = x;
        s += x;
        ss = fmaf(x, x, ss);
    }
    #pragma unroll
    for (int o = 16; o > 0; o >>= 1) {
        s += __shfl_xor_sync(0xffffffffu, s, o);
        ss += __shfl_xor_sync(0xffffffffu, ss, o);
    }
    if (lane == 0) { red_s[wid] = s; red_ss[wid] = ss; }
    __syncthreads();
    const int rb = grp * 4;
    float ts = red_s[rb] + red_s[rb + 1] + red_s[rb + 2] + red_s[rb + 3];
    float tss = red_ss[rb] + red_ss[rb + 1] + red_ss[rb + 2] + red_ss[rb + 3];
    const float mu = ts * (1.0f / (float)D);
    const float rstd = rsqrtf(tss * (1.0f / (float)D) - mu * mu + 1e-5f);

    const float sw0 = __ldg(&sem[c * 4 + 0]);
    const float sw1 = __ldg(&sem[c * 4 + 1]);
    const float sw2 = __ldg(&sem[c * 4 + 2]);
    const float4 tA = __ldg(&g_tokA[n]);
    const float2 tB = __ldg(&g_tokB[n]);

    const float* nrow = noise + (size_t)n * D;
    float4* orow = out + (size_t)n * D;

    #pragma unroll
    for (int k = 0; k < 4; k++) {
        const int d = k * 128 + gt;
        float y = (xw[k] - mu) * rstd * colr[k].y + colr[k].z + 0.01f * __ldcs(&nrow[d]);
        float4 ph = phr[k];
        float4 o;
        o.x = y;
        o.y = y * sw0 * (ph.x * tA.x - ph.y * tA.y);   // cos(phase + cpm)
        o.z = y * sw1 * (ph.y * tA.z + ph.x * tA.w);   // sin(phase + 1.3cpm)
        o.w = y * sw2 * (ph.z * tB.x - ph.w * tB.y);   // cos(2phase + 0.7cpm)
        __stcs(&orow[d], o);
    }
}

// ---------------- launch ----------------
extern "C" void kernel_launch(void* const* d_in, const int* in_sizes, int n_in,
                              void* d_out, int out_size) {
    const int*   char_idx  = (const int*)d_in[0];
    const int*   positions = (const int*)d_in[1];
    const float* W         = (const float*)d_in[2];
    const float* b         = (const float*)d_in[3];
    const float* gamma     = (const float*)d_in[4];
    const float* beta_ln   = (const float*)d_in[5];
    const float* noise     = (const float*)d_in[6];
    const float* sem       = (const float*)d_in[7];
    float4* out = (float4*)d_out;

    setup_kernel<<<(VOCAB * D) / 256, 256>>>(char_idx, positions, b, gamma, beta_ln);
    vgemm_kernel<<<dim3(VOCAB, 4), 128>>>(W);
    main_kernel<<<N_TOK / 2, 256>>>(char_idx, noise, sem, out);
}

// round 8
// speedup vs baseline: 6.0441x; 1.2889x over previous
#include <cuda_runtime.h>
#include <math.h>
#include <stdint.h>

#define N_TOK 16384
#define D 512
#define VOCAB 96

// ---------------- device scratch ----------------
__device__ float4 g_U[VOCAB * D];    // (u1r, u1i, u2r, u2i) per (char, d)
__device__ float4 g_V[VOCAB * D];    // (V1r, V1i, V2r, V2i) = U @ W^T
__device__ float4 g_S[VOCAB];        // (S11, S22, S12r, S12i)
__device__ float4 g_phtab[D];        // cosP, sinP, cos2P, sin2P
__device__ float4 g_cols[D];         // bias, gamma, beta, 0
__device__ float4 g_wf[N_TOK];       // wf1r, wf1i, wf2r, wf2i
__device__ float4 g_tokA[N_TOK];     // cos(cpm), sin(cpm), cos(1.3cpm), sin(1.3cpm)
__device__ float2 g_tokB[N_TOK];     // cos(.7cpm), sin(.7cpm)

// ---------------- K0: all trig, fully parallel ----------------
__global__ __launch_bounds__(256) void setup_kernel(const int* __restrict__ char_idx,
                                                    const int* __restrict__ positions,
                                                    const float* __restrict__ bias,
                                                    const float* __restrict__ gamma,
                                                    const float* __restrict__ beta_ln) {
    const int gid = blockIdx.x * blockDim.x + threadIdx.x;
    const float PI = 3.14159265358979323846f;

    // ---- U table entry ----
    {
        int c = gid / D, d = gid % D;
        float kv = (float)d + 1.0f;
        float s1, c1, s2, c2;
        sincosf(1.5f * atanf(logf(kv + 1e-10f)), &s1, &c1);
        sincosf(0.8f * sinf(0.1f * kv), &s2, &c2);
        float fr = 0.7f * c1 + 0.3f * c2;
        float fi = 0.7f * s1 + 0.3f * s2;
        float w1 = 0.6f + 0.4f * sinf(0.1f * (float)d);
        float w2 = 0.4f + 0.6f * cosf(0.15f * (float)d);

        float prod = (float)c * (float)d;
        float s, co;
        sincosf(2.0f * PI * prod * (1.0f / ((float)VOCAB * (float)D)), &s, &co);
        float u1r = w1 * (co * fr - s * fi), u1i = w1 * (co * fi + s * fr);
        sincosf((4.0f * PI * 1.7f) * prod * (1.0f / ((float)VOCAB * (float)D)), &s, &co);
        float u2r = w2 * (co * fr - s * fi), u2i = w2 * (co * fi + s * fr);
        g_U[gid] = make_float4(u1r, u1i, u2r, u2i);
    }

    if (gid < D) {
        float ph = 2.0f * PI * (float)gid * (1.0f / (float)D);
        float sp, cp, s2p, c2p;
        sincosf(ph, &sp, &cp);
        sincosf(2.0f * ph, &s2p, &c2p);
        g_phtab[gid] = make_float4(cp, sp, c2p, s2p);
        g_cols[gid] = make_float4(bias[gid], gamma[gid], beta_ln[gid], 0.f);
    }

    if (gid < N_TOK) {
        int ci = char_idx[gid];
        float lam = (float)ci * (1.0f / (float)VOCAB);
        float t = (float)positions[gid] * 0.01f;
        float omega = 2.0f * PI * 1.5f;
        float kwav = 2.0f * PI / 1.7f;
        float ph1 = omega * t - kwav * lam + 0.8f * lam * lam;
        float ph2 = omega * t * 1.5f - kwav * lam * 0.7f + 0.8f * lam * lam * 1.3f;
        float a1 = sinf(omega * t + 1.5f * lam);
        float a2 = cosf(omega * t * 0.8f + 1.5f * lam * 1.2f);
        float s, cc;
        sincosf(ph1, &s, &cc);
        float wf1r = a1 * cc, wf1i = a1 * s;
        sincosf(ph2, &s, &cc);
        float wf2r = a2 * cc, wf2i = a2 * s;
        g_wf[gid] = make_float4(wf1r, wf1i, wf2r, wf2i);

        float cpm = (float)ci * 0.01f;
        float s0, c0, sb, cb, sc, ccc;
        sincosf(cpm, &s0, &c0);
        sincosf(cpm * 1.3f, &sb, &cb);
        sincosf(cpm * 0.7f, &sc, &ccc);
        g_tokA[gid] = make_float4(c0, s0, cb, sb);
        g_tokB[gid] = make_float2(ccc, sc);
    }
}

// ---------------- K1: tiled V gemm + Gram sums, 2 chars per block ----------------
// grid (48, 4), 128 threads. Block (cg, q): chars {2cg, 2cg+1}, columns [q*128, q*128+128).
__global__ __launch_bounds__(128) void vgemm_kernel(const float* __restrict__ W) {
    const int c0 = blockIdx.x * 2;
    const int q = blockIdx.y;
    const int tid = threadIdx.x;

    __shared__ float4 su[2][D];       // U rows for the two chars
    __shared__ float tile[128][33];   // W sub-tile, padded stride
    __shared__ float sm[4][4];

    #pragma unroll
    for (int l = 0; l < 4; l++) {
        su[0][tid + l * 128] = __ldg(&g_U[(c0 + 0) * D + tid + l * 128]);
        su[1][tid + l * 128] = __ldg(&g_U[(c0 + 1) * D + tid + l * 128]);
    }
    __syncthreads();

    if (q == 0) {
        #pragma unroll
        for (int cc = 0; cc < 2; cc++) {
            float s11 = 0.f, s22 = 0.f, s12r = 0.f, s12i = 0.f;
            #pragma unroll
            for (int l = 0; l < 4; l++) {
                float4 u = su[cc][tid + l * 128];
                s11 += u.x * u.x + u.y * u.y;
                s22 += u.z * u.z + u.w * u.w;
                s12r += u.x * u.z + u.y * u.w;
                s12i += u.y * u.z - u.x * u.w;
            }
            #pragma unroll
            for (int o = 16; o > 0; o >>= 1) {
                s11 += __shfl_xor_sync(0xffffffffu, s11, o);
                s22 += __shfl_xor_sync(0xffffffffu, s22, o);
                s12r += __shfl_xor_sync(0xffffffffu, s12r, o);
                s12i += __shfl_xor_sync(0xffffffffu, s12i, o);
            }
            if ((tid & 31) == 0) {
                int w = tid >> 5;
                sm[0][w] = s11; sm[1][w] = s22; sm[2][w] = s12r; sm[3][w] = s12i;
            }
            __syncthreads();
            if (tid == 0) {
                g_S[c0 + cc] = make_float4(sm[0][0] + sm[0][1] + sm[0][2] + sm[0][3],
                                           sm[1][0] + sm[1][1] + sm[1][2] + sm[1][3],
                                           sm[2][0] + sm[2][1] + sm[2][2] + sm[2][3],
                                           sm[3][0] + sm[3][1] + sm[3][2] + sm[3][3]);
            }
            __syncthreads();
        }
    }

    // ---- tiled GEMM: 16 chunks of 32 k-values, 2 chars at once ----
    const int dpbase = q * 128;
    float a1r = 0.f, a1i = 0.f, a2r = 0.f, a2i = 0.f;   // char c0
    float b1r = 0.f, b1i = 0.f, b2r = 0.f, b2i = 0.f;   // char c0+1

    #pragma unroll 1
    for (int chunk = 0; chunk < 16; chunk++) {
        const int dk = chunk * 32;
        __syncthreads();
        #pragma unroll
        for (int l = 0; l < 8; l++) {
            int f = tid + l * 128;
            int row = f >> 3, col4 = (f & 7) * 4;
            float4 w = *(const float4*)(W + (size_t)(dpbase + row) * D + dk + col4);
            tile[row][col4 + 0] = w.x;
            tile[row][col4 + 1] = w.y;
            tile[row][col4 + 2] = w.z;
            tile[row][col4 + 3] = w.w;
        }
        __syncthreads();
        #pragma unroll
        for (int k = 0; k < 32; k++) {
            float wv = tile[tid][k];
            float4 u = su[0][dk + k];
            float4 v = su[1][dk + k];
            a1r = fmaf(u.x, wv, a1r);
            a1i = fmaf(u.y, wv, a1i);
            a2r = fmaf(u.z, wv, a2r);
            a2i = fmaf(u.w, wv, a2i);
            b1r = fmaf(v.x, wv, b1r);
            b1i = fmaf(v.y, wv, b1i);
            b2r = fmaf(v.z, wv, b2r);
            b2i = fmaf(v.w, wv, b2i);
        }
    }
    g_V[(c0 + 0) * D + dpbase + tid] = make_float4(a1r, a1i, a2r, a2i);
    g_V[(c0 + 1) * D + dpbase + tid] = make_float4(b1r, b1i, b2r, b2i);
}

// ---------------- K2: fused coef + xw + LayerNorm + noise + quaternion ----------
// One token per 128-thread group; 2 tokens per 256-thread block; 5 blocks/SM.
__global__ __launch_bounds__(256, 5) void main_kernel(const int* __restrict__ char_idx,
                                                      const float* __restrict__ noise,
                                                      const float* __restrict__ sem,
                                                      float4* __restrict__ out) {
    __shared__ float red_s[8], red_ss[8];

    const int tid = threadIdx.x;
    const int grp = tid >> 7;
    const int gt = tid & 127;
    const int lane = tid & 31;
    const int wid = tid >> 5;
    const int n = blockIdx.x * 2 + grp;

    // register-resident per-d tables (d = k*128 + gt, fixed per thread)
    float4 colr[4], phr[4];
    #pragma unroll
    for (int k = 0; k < 4; k++) {
        colr[k] = __ldg(&g_cols[k * 128 + gt]);
        phr[k]  = __ldg(&g_phtab[k * 128 + gt]);
    }

    const int c = __ldg(&char_idx[n]);
    const float4 wf = __ldg(&g_wf[n]);
    const float4 S = __ldg(&g_S[c]);

    // per-token coefficients
    float n1 = wf.x * wf.x + wf.y * wf.y;
    float n2 = wf.z * wf.z + wf.w * wf.w;
    float Ar = wf.x * wf.z + wf.y * wf.w;
    float Ai = wf.y * wf.z - wf.x * wf.w;
    float nrm2 = n1 * S.x + n2 * S.y + 2.0f * (Ar * S.z - Ai * S.w);
    float rinv = 1.0f / (sqrtf(nrm2) + 1e-8f);
    const float ct = 0.995004165278025766f;
    const float st = 0.0998334166468281523f;
    const float p1 = (wf.x * ct - wf.y * st) * rinv;
    const float q1 = -(wf.y * ct + wf.x * st) * rinv;
    const float p2 = (wf.z * ct - wf.w * st) * rinv;
    const float q2 = -(wf.w * ct + wf.z * st) * rinv;

    // 4 columns per thread, coalesced V reads; noise prefetched to overlap reduction
    const float4* vrow = g_V + c * D;
    const float* nrow = noise + (size_t)n * D;
    float xw[4], nz[4];
    float s = 0.f, ss = 0.f;
    #pragma unroll
    for (int k = 0; k < 4; k++) {
        const int d = k * 128 + gt;
        float4 v = __ldg(&vrow[d]);
        nz[k] = __ldcs(&nrow[d]);
        float x = fmaf(p1, v.x, fmaf(q1, v.y, fmaf(p2, v.z, q2 * v.w))) + colr[k].x;
        xw[k] = x;
        s += x;
        ss = fmaf(x, x, ss);
    }
    #pragma unroll
    for (int o = 16; o > 0; o >>= 1) {
        s += __shfl_xor_sync(0xffffffffu, s, o);
        ss += __shfl_xor_sync(0xffffffffu, ss, o);
    }
    if (lane == 0) { red_s[wid] = s; red_ss[wid] = ss; }
    __syncthreads();
    const int rb = grp * 4;
    float ts = red_s[rb] + red_s[rb + 1] + red_s[rb + 2] + red_s[rb + 3];
    float tss = red_ss[rb] + red_ss[rb + 1] + red_ss[rb + 2] + red_ss[rb + 3];
    const float mu = ts * (1.0f / (float)D);
    const float rstd = rsqrtf(tss * (1.0f / (float)D) - mu * mu + 1e-5f);

    const float sw0 = __ldg(&sem[c * 4 + 0]);
    const float sw1 = __ldg(&sem[c * 4 + 1]);
    const float sw2 = __ldg(&sem[c * 4 + 2]);
    const float4 tA = __ldg(&g_tokA[n]);
    const float2 tB = __ldg(&g_tokB[n]);

    float4* orow = out + (size_t)n * D;

    #pragma unroll
    for (int k = 0; k < 4; k++) {
        const int d = k * 128 + gt;
        float y = (xw[k] - mu) * rstd * colr[k].y + colr[k].z + 0.01f * nz[k];
        float4 ph = phr[k];
        float4 o;
        o.x = y;
        o.y = y * sw0 * (ph.x * tA.x - ph.y * tA.y);   // cos(phase + cpm)
        o.z = y * sw1 * (ph.y * tA.z + ph.x * tA.w);   // sin(phase + 1.3cpm)
        o.w = y * sw2 * (ph.z * tB.x - ph.w * tB.y);   // cos(2phase + 0.7cpm)
        __stcs(&orow[d], o);
    }
}

// ---------------- launch ----------------
extern "C" void kernel_launch(void* const* d_in, const int* in_sizes, int n_in,
                              void* d_out, int out_size) {
    const int*   char_idx  = (const int*)d_in[0];
    const int*   positions = (const int*)d_in[1];
    const float* W         = (const float*)d_in[2];
    const float* b         = (const float*)d_in[3];
    const float* gamma     = (const float*)d_in[4];
    const float* beta_ln   = (const float*)d_in[5];
    const float* noise     = (const float*)d_in[6];
    const float* sem       = (const float*)d_in[7];
    float4* out = (float4*)d_out;

    setup_kernel<<<(VOCAB * D) / 256, 256>>>(char_idx, positions, b, gamma, beta_ln);
    vgemm_kernel<<<dim3(VOCAB / 2, 4), 128>>>(W);
    main_kernel<<<N_TOK / 2, 256>>>(char_idx, noise, sem, out);
}